// round 14
// baseline (speedup 1.0000x reference)
#include <cuda_runtime.h>

// LatentLinearModel: r[i] = dot(U[users[i]], V[jokes[i]]) + a[users[i]] + b[jokes[i]] + g
// B = 1048576, K = 64.
//
// Round 14: deconfounded R13. The two-stage overlap (compute S0 while S1's
// 16KB is still in flight) dropped regs to 36 and accidentally seated a 6th
// resident block - and 6 blocks/SM has REPRODUCIBLY cost 3-5 points of DRAM%
// all session (R9/R10/R13). Here the staging is kept and residency is pinned
// back to the known-optimal 5 blocks/SM by padding static smem to ~39KB
// (228KB carveout / 39KB = 5 blocks). Everything else identical to R13.

#define TPR    16                   // threads per row
#define RPG    2                    // rows per 16-lane group PER STAGE
#define BLOCK  256
#define GROUPS (BLOCK / TPR)        // 16
#define SROWS  (GROUPS * RPG)       // 32 rows per stage
#define RPB    (2 * SROWS)          // 64 rows per block
#define SMEM_PAD 7168               // pad 32KB -> ~39KB: exactly 5 blocks/SM

__device__ __forceinline__ void cp_async16(void* smem, const void* gmem) {
    unsigned s = (unsigned)__cvta_generic_to_shared(smem);
    asm volatile("cp.async.cg.shared.global [%0], [%1], 16;" :: "r"(s), "l"(gmem));
}

__global__ void __launch_bounds__(BLOCK)
latent_linear_kernel(const int* __restrict__ users,
                     const int* __restrict__ jokes,
                     const float4* __restrict__ U4,
                     const float4* __restrict__ V4,
                     const float* __restrict__ a,
                     const float* __restrict__ b,
                     const float* __restrict__ g,
                     float* __restrict__ out,
                     int B) {
    __shared__ float4 sU[2][SROWS][TPR];   // 2 x 8 KB
    __shared__ float4 sV[2][SROWS][TPR];   // 2 x 8 KB
    __shared__ char   pad[SMEM_PAD];       // residency limiter (never touched)

    // Keep the pad alive: dynamically-false branch the compiler can't fold.
    if (B < 0) ((volatile char*)pad)[0] = 1;

    const int lane  = threadIdx.x & (TPR - 1);
    const int group = threadIdx.x >> 4;
    const int lr0   = group * RPG;                 // local row base within a stage
    const int base  = blockIdx.x * RPB;
    if (base >= B) return;

    const int r0s0 = base + lr0;                   // stage 0 rows
    const int r0s1 = base + SROWS + lr0;           // stage 1 rows

    // ---- Phase 1: index loads for BOTH stages ----
    int2 u0 = __ldg((const int2*)(users + r0s0));
    int2 j0 = __ldg((const int2*)(jokes + r0s0));
    int2 u1 = __ldg((const int2*)(users + r0s1));
    int2 j1 = __ldg((const int2*)(jokes + r0s1));
    int us[4] = {u0.x, u0.y, u1.x, u1.y};
    int js[4] = {j0.x, j0.y, j1.x, j1.y};

    // ---- Phase 2a: issue stage 0 gathers, commit ----
#pragma unroll
    for (int r = 0; r < RPG; r++) {
        cp_async16(&sU[0][lr0 + r][lane], &U4[(size_t)us[r] * 16 + lane]);
        cp_async16(&sV[0][lr0 + r][lane], &V4[(size_t)js[r] * 16 + lane]);
    }
    asm volatile("cp.async.commit_group;");

    // ---- Phase 2b: issue stage 1 gathers, commit ----
#pragma unroll
    for (int r = 0; r < RPG; r++) {
        cp_async16(&sU[1][lr0 + r][lane], &U4[(size_t)us[2 + r] * 16 + lane]);
        cp_async16(&sV[1][lr0 + r][lane], &V4[(size_t)js[2 + r] * 16 + lane]);
    }
    asm volatile("cp.async.commit_group;");

    // Bias loads fly concurrently with the gathers (lane 0 only, registers).
    float bias[4];
    if (lane == 0) {
#pragma unroll
        for (int r = 0; r < 4; r++)
            bias[r] = __ldg(&a[us[r]]) + __ldg(&b[js[r]]);
    }
    float gg = __ldg(&g[0]);

    // ---- Phase 3a: stage 0 compute overlaps stage 1 in-flight ----
    asm volatile("cp.async.wait_group 1;" ::: "memory");
#pragma unroll
    for (int r = 0; r < RPG; r++) {
        float4 uu = sU[0][lr0 + r][lane];
        float4 vv = sV[0][lr0 + r][lane];
        float d = uu.x * vv.x + uu.y * vv.y + uu.z * vv.z + uu.w * vv.w;
        d += __shfl_xor_sync(0xffffffffu, d, 8);
        d += __shfl_xor_sync(0xffffffffu, d, 4);
        d += __shfl_xor_sync(0xffffffffu, d, 2);
        d += __shfl_xor_sync(0xffffffffu, d, 1);
        if (lane == 0) {
            out[r0s0 + r] = d + bias[r] + gg;
        }
    }

    // ---- Phase 3b: stage 1 compute ----
    asm volatile("cp.async.wait_group 0;" ::: "memory");
#pragma unroll
    for (int r = 0; r < RPG; r++) {
        float4 uu = sU[1][lr0 + r][lane];
        float4 vv = sV[1][lr0 + r][lane];
        float d = uu.x * vv.x + uu.y * vv.y + uu.z * vv.z + uu.w * vv.w;
        d += __shfl_xor_sync(0xffffffffu, d, 8);
        d += __shfl_xor_sync(0xffffffffu, d, 4);
        d += __shfl_xor_sync(0xffffffffu, d, 2);
        d += __shfl_xor_sync(0xffffffffu, d, 1);
        if (lane == 0) {
            out[r0s1 + r] = d + bias[2 + r] + gg;
        }
    }
}

extern "C" void kernel_launch(void* const* d_in, const int* in_sizes, int n_in,
                              void* d_out, int out_size) {
    // metadata order: users, jokes, U, V, a, b, g
    const int*    users = (const int*)d_in[0];
    const int*    jokes = (const int*)d_in[1];
    const float4* U4    = (const float4*)d_in[2];
    const float4* V4    = (const float4*)d_in[3];
    const float*  a     = (const float*)d_in[4];
    const float*  b     = (const float*)d_in[5];
    const float*  g     = (const float*)d_in[6];
    float* out = (float*)d_out;

    int B = in_sizes[0];

    int grid = (B + RPB - 1) / RPB;
    latent_linear_kernel<<<grid, BLOCK>>>(users, jokes, U4, V4, a, b, g, out, B);
}

// round 15
// speedup vs baseline: 1.2436x; 1.2436x over previous
#include <cuda_runtime.h>

// LatentLinearModel: r[i] = dot(U[users[i]], V[jokes[i]]) + a[users[i]] + b[jokes[i]] + g
// B = 1048576, K = 64.
//
// FINAL = Round 4 (measured 59.9us, reproduced 60.1us in R11).
// 14-round session summary: this workload is a random 256B-row gather with
// ~291MB irreducible traffic; it saturates at ~61% of HBM peak (random-access
// DRAM efficiency ceiling). This configuration is a sharp local optimum:
//   - 16 threads/row, 16B/lane: each 256B row = exactly two full 128B lines,
//     zero gather waste.
//   - 4 rows per 16-lane group; all 8 gathers issued as ONE cp.async burst
//     (32KB/block) before any consumption -> in-flight bytes live in smem,
//     registers stay at 44 -> 5 blocks/SM, which exactly fills the per-SM
//     L1tex in-flight queue (6 blocks measurably degrades DRAM throughput;
//     splitting the burst into stages degrades it; persistence, reordering,
//     L2 hints, and the TMA-bulk engine all degrade it).
//   - biases via register __ldg overlapping the gather window; coalesced
//     index loads (int4) and output stores.

#define TPR    16                   // threads per row
#define RPG    4                    // rows per 16-lane group
#define BLOCK  256
#define GROUPS (BLOCK / TPR)        // 16
#define RPB    (GROUPS * RPG)       // 64 rows per block

__device__ __forceinline__ void cp_async16(void* smem, const void* gmem) {
    unsigned s = (unsigned)__cvta_generic_to_shared(smem);
    asm volatile("cp.async.cg.shared.global [%0], [%1], 16;" :: "r"(s), "l"(gmem));
}

__global__ void __launch_bounds__(BLOCK)
latent_linear_kernel(const int* __restrict__ users,
                     const int* __restrict__ jokes,
                     const float4* __restrict__ U4,
                     const float4* __restrict__ V4,
                     const float* __restrict__ a,
                     const float* __restrict__ b,
                     const float* __restrict__ g,
                     float* __restrict__ out,
                     int B) {
    __shared__ float4 sU[RPB][TPR];   // 16 KB
    __shared__ float4 sV[RPB][TPR];   // 16 KB

    int lane  = threadIdx.x & (TPR - 1);
    int group = threadIdx.x >> 4;
    int lrow0 = group * RPG;                       // local row base in smem
    int row0  = blockIdx.x * RPB + lrow0;          // global row base
    if (row0 >= B) return;

    // ---- Phase 1: vectorized index loads (row0 multiple of 4 -> 16B aligned) ----
    int4 ui = __ldg((const int4*)(users + row0));
    int4 ji = __ldg((const int4*)(jokes + row0));
    int us[RPG] = {ui.x, ui.y, ui.z, ui.w};
    int js[RPG] = {ji.x, ji.y, ji.z, ji.w};

    // ---- Phase 2: issue all 8 gathers per thread as one cp.async burst ----
#pragma unroll
    for (int r = 0; r < RPG; r++) {
        cp_async16(&sU[lrow0 + r][lane], &U4[(size_t)us[r] * 16 + lane]);
        cp_async16(&sV[lrow0 + r][lane], &V4[(size_t)js[r] * 16 + lane]);
    }
    asm volatile("cp.async.commit_group;");

    // Bias loads fly concurrently with the cp.asyncs (lane 0 only).
    float bias[RPG];
    if (lane == 0) {
#pragma unroll
        for (int r = 0; r < RPG; r++) {
            bias[r] = __ldg(&a[us[r]]) + __ldg(&b[js[r]]);
        }
    }
    float gg = __ldg(&g[0]);

    asm volatile("cp.async.wait_group 0;" ::: "memory");

    // ---- Phase 3: dot + 16-lane reduction per row (thread-private smem slots) ----
#pragma unroll
    for (int r = 0; r < RPG; r++) {
        float4 uu = sU[lrow0 + r][lane];
        float4 vv = sV[lrow0 + r][lane];
        float d = uu.x * vv.x + uu.y * vv.y + uu.z * vv.z + uu.w * vv.w;
        d += __shfl_xor_sync(0xffffffffu, d, 8);
        d += __shfl_xor_sync(0xffffffffu, d, 4);
        d += __shfl_xor_sync(0xffffffffu, d, 2);
        d += __shfl_xor_sync(0xffffffffu, d, 1);
        if (lane == 0) {
            out[row0 + r] = d + bias[r] + gg;
        }
    }
}

extern "C" void kernel_launch(void* const* d_in, const int* in_sizes, int n_in,
                              void* d_out, int out_size) {
    // metadata order: users, jokes, U, V, a, b, g
    const int*    users = (const int*)d_in[0];
    const int*    jokes = (const int*)d_in[1];
    const float4* U4    = (const float4*)d_in[2];
    const float4* V4    = (const float4*)d_in[3];
    const float*  a     = (const float*)d_in[4];
    const float*  b     = (const float*)d_in[5];
    const float*  g     = (const float*)d_in[6];
    float* out = (float*)d_out;

    int B = in_sizes[0];

    int grid = (B + RPB - 1) / RPB;
    latent_linear_kernel<<<grid, BLOCK>>>(users, jokes, U4, V4, a, b, g, out, B);
}